// round 9
// baseline (speedup 1.0000x reference)
// R9: linearity restructure — aggregate-then-project; k_gemm eliminated.
#include <cuda_runtime.h>
#include <cuda_fp16.h>
#include <math.h>
#include <float.h>

#define NN 100000
#define EE 1200000
#define FD 64
#define NG 1024
#define NT 12
#define CHID 128
#define EPS 1e-5f
#define NB1 98   // (NN+1023)/1024

// ---------------- scratch ----------------
__device__ __half g_xh[(size_t)NN * FD];   // fp16 copy of layer input (gather source)
__device__ __half g_h1h[(size_t)NN * FD];  // fp16 copy of h1
__device__ float g_h1[(size_t)NN * FD];
__device__ float g_h2[(size_t)NN * FD];
__device__ float g_w[NN];
__device__ int   g_deg[NN + 1];
__device__ int   g_off[NN + 1];   // block-local exclusive prefix
__device__ int   g_cur[NN];       // scatter cursors (zeroed)
__device__ int   g_esrc[EE];
__device__ int   g_bsum[128];
__device__ int   g_bpre[128];
__device__ float g_stats1[2 * FD];
__device__ float g_stats2[2 * FD];
__device__ float g_statsC[2 * CHID];
__device__ float g_hg[(size_t)NG * 2 * FD];
__device__ float g_z[(size_t)NG * CHID];

// ---------------- zero ----------------
__global__ void k_zero() {
    int i = blockIdx.x * blockDim.x + threadIdx.x;
    if (i < NN + 1) g_deg[i] = 0;
    if (i < NN) g_cur[i] = 0;
    if (i < 2 * FD) { g_stats1[i] = 0.f; g_stats2[i] = 0.f; }
    if (i < 2 * CHID) g_statsC[i] = 0.f;
}

// ---------------- fp32 -> fp16 convert (gather source) ----------------
__global__ void k_cvt(const float* __restrict__ x, __half* __restrict__ o) {
    int i = blockIdx.x * blockDim.x + threadIdx.x;
    if (i < NN * FD / 4) {
        float4 v = ((const float4*)x)[i];
        __half2 a = __floats2half2_rn(v.x, v.y);
        __half2 b = __floats2half2_rn(v.z, v.w);
        ((uint2*)o)[i] = make_uint2(*(unsigned*)&a, *(unsigned*)&b);
    }
}

// ---------------- CSR build ----------------
__global__ void k_deg(const int* __restrict__ dst) {
    int i = blockIdx.x * blockDim.x + threadIdx.x;
    if (i < EE / 4) {
        int4 d = ((const int4*)dst)[i];
        atomicAdd(&g_deg[d.x], 1);
        atomicAdd(&g_deg[d.y], 1);
        atomicAdd(&g_deg[d.z], 1);
        atomicAdd(&g_deg[d.w], 1);
    }
}

__global__ __launch_bounds__(1024) void k_scan1() {
    int tid = threadIdx.x;
    int i = blockIdx.x * 1024 + tid;
    int d = (i < NN) ? g_deg[i] : 0;
    int lane = tid & 31, wid = tid >> 5;
    int v = d;
    #pragma unroll
    for (int o = 1; o < 32; o <<= 1) {
        int t = __shfl_up_sync(0xffffffffu, v, o);
        if (lane >= o) v += t;
    }
    __shared__ int ws[32];
    if (lane == 31) ws[wid] = v;
    __syncthreads();
    if (wid == 0) {
        int u = ws[lane];
        #pragma unroll
        for (int o = 1; o < 32; o <<= 1) {
            int t = __shfl_up_sync(0xffffffffu, u, o);
            if (lane >= o) u += t;
        }
        ws[lane] = u;
    }
    __syncthreads();
    int base = wid ? ws[wid - 1] : 0;
    if (i < NN) g_off[i] = base + v - d;
    if (tid == 0) g_bsum[blockIdx.x] = ws[31];
}

__global__ void k_scan2() {
    __shared__ int sh[128];
    int tid = threadIdx.x;
    int v = (tid < NB1) ? g_bsum[tid] : 0;
    sh[tid] = v;
    __syncthreads();
    for (int o = 1; o < 128; o <<= 1) {
        int t = (tid >= o) ? sh[tid - o] : 0;
        __syncthreads();
        sh[tid] += t;
        __syncthreads();
    }
    if (tid < NB1) g_bpre[tid] = sh[tid] - v;
}

__global__ void k_scatter(const int* __restrict__ src, const int* __restrict__ dst) {
    int i = blockIdx.x * blockDim.x + threadIdx.x;
    if (i < EE / 4) {
        int4 s = ((const int4*)src)[i];
        int4 d = ((const int4*)dst)[i];
        int o0 = __ldg(&g_off[d.x]) + __ldg(&g_bpre[d.x >> 10]);
        int o1 = __ldg(&g_off[d.y]) + __ldg(&g_bpre[d.y >> 10]);
        int o2 = __ldg(&g_off[d.z]) + __ldg(&g_bpre[d.z >> 10]);
        int o3 = __ldg(&g_off[d.w]) + __ldg(&g_bpre[d.w >> 10]);
        g_esrc[o0 + atomicAdd(&g_cur[d.x], 1)] = s.x;
        g_esrc[o1 + atomicAdd(&g_cur[d.y], 1)] = s.y;
        g_esrc[o2 + atomicAdd(&g_cur[d.z], 1)] = s.z;
        g_esrc[o3 + atomicAdd(&g_cur[d.w], 1)] = s.w;
    }
}

__device__ __forceinline__ int node_off(int v) {
    return g_off[v] + g_bpre[v >> 10];
}

// ---- fused layer: gather raw fp16 x -> agg; (agg*sc+deg*sh)@W; BN(x)@rW; epilogue ----
// h = relu(agg_norm@W + b) + relu(BN(x)@rW + rb); writes h fp32 (+ optional fp16); BN stats.
__global__ __launch_bounds__(256) void k_layer(
    const float* __restrict__ x, const __half* __restrict__ xh,
    const float* __restrict__ stats, const float* __restrict__ gamma, const float* __restrict__ beta,
    const float* __restrict__ W, const float* __restrict__ bias,
    const float* __restrict__ rW, const float* __restrict__ rb,
    float* __restrict__ outh, __half* __restrict__ outh_h,
    float* __restrict__ stats_out)
{
    __shared__ float A[64][68];    // agg tile, then BN(x) tile
    __shared__ float B[64][64];    // W, then rW
    __shared__ float scb[64], shb[64];
    __shared__ float s_sum[64], s_sq[64];
    int tid = threadIdx.x;
    int lane = tid & 31, wi = tid >> 5;

    if (tid < 64) {
        float sc = 1.f, sh = 0.f;
        if (stats) {
            float mu  = stats[tid] * (1.f / NN);
            float var = stats[64 + tid] * (1.f / NN) - mu * mu;
            float rs  = rsqrtf(var + EPS);
            sc = gamma[tid] * rs;
            sh = beta[tid] - mu * sc;
        }
        scb[tid] = sc; shb[tid] = sh;
        s_sum[tid] = 0.f; s_sq[tid] = 0.f;
    }
    // load W into B
    #pragma unroll
    for (int q = 0; q < 16; q++) {
        int lin = tid + q * 256;
        ((float*)B)[lin] = W[lin];
    }
    __syncthreads();   // scb/shb visible for gather correction

    int row0 = blockIdx.x * 64;

    // ---- gather phase: warp split into two 16-lane halves, one node each ----
    // aggregates raw fp16 x over in-edges; applies BN affine: agg*sc + deg*sh
    {
        const uint2* m4 = (const uint2*)xh;          // 16 uint2 per node row
        int lane16 = lane & 15;
        int hbase  = lane & 16;                       // 0 or 16
        for (int t = 0; t < 4; t++) {
            int r = wi * 8 + t * 2 + (hbase >> 4);
            int v = row0 + r;
            float a0 = 0.f, a1 = 0.f, a2 = 0.f, a3 = 0.f;
            int s = 0, cnt = 0;
            if (v < NN) {
                s = node_off(v);
                int e = (v + 1 < NN) ? node_off(v + 1) : EE;
                cnt = e - s;
            }
            int cnt_o = __shfl_xor_sync(0xffffffffu, cnt, 16);
            int iters = max(cnt, cnt_o);
            for (int base = 0; base < iters; base += 16) {
                int my = base + lane16;
                int idx = (my < cnt) ? __ldg(&g_esrc[s + my]) : -1;
                #pragma unroll
                for (int g = 0; g < 16; g += 4) {
                    int s0 = __shfl_sync(0xffffffffu, idx, hbase + g + 0);
                    int s1 = __shfl_sync(0xffffffffu, idx, hbase + g + 1);
                    int s2 = __shfl_sync(0xffffffffu, idx, hbase + g + 2);
                    int s3 = __shfl_sync(0xffffffffu, idx, hbase + g + 3);
                    uint2 z = make_uint2(0u, 0u);
                    uint2 q0 = (s0 >= 0) ? __ldg(&m4[(size_t)s0 * 16 + lane16]) : z;
                    uint2 q1 = (s1 >= 0) ? __ldg(&m4[(size_t)s1 * 16 + lane16]) : z;
                    uint2 q2 = (s2 >= 0) ? __ldg(&m4[(size_t)s2 * 16 + lane16]) : z;
                    uint2 q3 = (s3 >= 0) ? __ldg(&m4[(size_t)s3 * 16 + lane16]) : z;
                    float2 f0a = __half22float2(*(__half2*)&q0.x), f0b = __half22float2(*(__half2*)&q0.y);
                    float2 f1a = __half22float2(*(__half2*)&q1.x), f1b = __half22float2(*(__half2*)&q1.y);
                    float2 f2a = __half22float2(*(__half2*)&q2.x), f2b = __half22float2(*(__half2*)&q2.y);
                    float2 f3a = __half22float2(*(__half2*)&q3.x), f3b = __half22float2(*(__half2*)&q3.y);
                    a0 += (f0a.x + f1a.x) + (f2a.x + f3a.x);
                    a1 += (f0a.y + f1a.y) + (f2a.y + f3a.y);
                    a2 += (f0b.x + f1b.x) + (f2b.x + f3b.x);
                    a3 += (f0b.y + f1b.y) + (f2b.y + f3b.y);
                }
            }
            // BN affine correction: sum(BN(x)) = sum(x)*sc + deg*sh
            int c = lane16 * 4;
            float dc = (float)cnt;
            float4 o;
            o.x = a0 * scb[c + 0] + dc * shb[c + 0];
            o.y = a1 * scb[c + 1] + dc * shb[c + 1];
            o.z = a2 * scb[c + 2] + dc * shb[c + 2];
            o.w = a3 * scb[c + 3] + dc * shb[c + 3];
            *(float4*)&A[r][c] = o;
        }
    }
    __syncthreads();

    int tx = tid & 15, ty = tid >> 4;
    int r0 = ty * 4, c0 = tx * 4;

    // ---- GEMM1: acc1 = agg_norm @ W ----
    float acc1[4][4] = {};
    #pragma unroll 4
    for (int k4 = 0; k4 < 64; k4 += 4) {
        float4 av[4];
        av[0] = *(const float4*)&A[r0 + 0][k4];
        av[1] = *(const float4*)&A[r0 + 1][k4];
        av[2] = *(const float4*)&A[r0 + 2][k4];
        av[3] = *(const float4*)&A[r0 + 3][k4];
        #pragma unroll
        for (int kk = 0; kk < 4; kk++) {
            float4 b = *(const float4*)&B[k4 + kk][c0];
            #pragma unroll
            for (int i = 0; i < 4; i++) {
                float a = (&av[i].x)[kk];
                acc1[i][0] += a * b.x; acc1[i][1] += a * b.y;
                acc1[i][2] += a * b.z; acc1[i][3] += a * b.w;
            }
        }
    }
    __syncthreads();   // done with A (agg) and B (W)

    // ---- reload: A = BN(x) tile, B = rW ----
    #pragma unroll
    for (int q = 0; q < 16; q++) {
        int lin = tid + q * 256;
        ((float*)B)[lin] = rW[lin];
    }
    #pragma unroll
    for (int q = 0; q < 4; q++) {
        int lin = tid + q * 256;
        int r = lin >> 4;
        int c4 = (lin & 15) * 4;
        float4 v = make_float4(0.f, 0.f, 0.f, 0.f);
        if (row0 + r < NN) v = *(const float4*)(x + (size_t)(row0 + r) * 64 + c4);
        float4 o;
        o.x = v.x * scb[c4 + 0] + shb[c4 + 0];
        o.y = v.y * scb[c4 + 1] + shb[c4 + 1];
        o.z = v.z * scb[c4 + 2] + shb[c4 + 2];
        o.w = v.w * scb[c4 + 3] + shb[c4 + 3];
        *(float4*)&A[r][c4] = o;
    }
    __syncthreads();

    // ---- GEMM2: acc2 = BN(x) @ rW ----
    float acc2[4][4] = {};
    #pragma unroll 4
    for (int k4 = 0; k4 < 64; k4 += 4) {
        float4 av[4];
        av[0] = *(const float4*)&A[r0 + 0][k4];
        av[1] = *(const float4*)&A[r0 + 1][k4];
        av[2] = *(const float4*)&A[r0 + 2][k4];
        av[3] = *(const float4*)&A[r0 + 3][k4];
        #pragma unroll
        for (int kk = 0; kk < 4; kk++) {
            float4 b = *(const float4*)&B[k4 + kk][c0];
            #pragma unroll
            for (int i = 0; i < 4; i++) {
                float a = (&av[i].x)[kk];
                acc2[i][0] += a * b.x; acc2[i][1] += a * b.y;
                acc2[i][2] += a * b.z; acc2[i][3] += a * b.w;
            }
        }
    }

    // ---- epilogue ----
    float4 b4  = *(const float4*)(bias + c0);
    float4 rb4 = *(const float4*)(rb + c0);
    float lsum[4] = {0.f, 0.f, 0.f, 0.f};
    float lsq[4]  = {0.f, 0.f, 0.f, 0.f};
    #pragma unroll
    for (int i = 0; i < 4; i++) {
        int r = row0 + r0 + i;
        if (r < NN) {
            float h0 = fmaxf(acc1[i][0] + b4.x, 0.f) + fmaxf(acc2[i][0] + rb4.x, 0.f);
            float h1 = fmaxf(acc1[i][1] + b4.y, 0.f) + fmaxf(acc2[i][1] + rb4.y, 0.f);
            float h2 = fmaxf(acc1[i][2] + b4.z, 0.f) + fmaxf(acc2[i][2] + rb4.z, 0.f);
            float h3 = fmaxf(acc1[i][3] + b4.w, 0.f) + fmaxf(acc2[i][3] + rb4.w, 0.f);
            *(float4*)(outh + (size_t)r * 64 + c0) = make_float4(h0, h1, h2, h3);
            if (outh_h) {
                __half2 p0 = __floats2half2_rn(h0, h1);
                __half2 p1 = __floats2half2_rn(h2, h3);
                *(uint2*)(outh_h + (size_t)r * 64 + c0) = make_uint2(*(unsigned*)&p0, *(unsigned*)&p1);
            }
            lsum[0] += h0; lsq[0] += h0 * h0;
            lsum[1] += h1; lsq[1] += h1 * h1;
            lsum[2] += h2; lsq[2] += h2 * h2;
            lsum[3] += h3; lsq[3] += h3 * h3;
        }
    }
    #pragma unroll
    for (int j = 0; j < 4; j++) {
        atomicAdd(&s_sum[c0 + j], lsum[j]);
        atomicAdd(&s_sq[c0 + j], lsq[j]);
    }
    __syncthreads();
    if (tid < 64) {
        atomicAdd(&stats_out[tid], s_sum[tid]);
        atomicAdd(&stats_out[64 + tid], s_sq[tid]);
    }
}

// ---------------- atom weights ----------------
__global__ __launch_bounds__(256) void k_wts(
    const float* __restrict__ gamma, const float* __restrict__ beta,
    const float* __restrict__ awW, const float* __restrict__ awb)
{
    int gt = blockIdx.x * blockDim.x + threadIdx.x;
    int v = gt >> 5;
    int lane = gt & 31;
    if (v >= NN) return;
    int f0 = 2 * lane, f1 = f0 + 1;
    float mu0  = g_stats2[f0] * (1.f / NN);
    float var0 = g_stats2[64 + f0] * (1.f / NN) - mu0 * mu0;
    float sc0  = gamma[f0] * rsqrtf(var0 + EPS);
    float sh0  = beta[f0] - mu0 * sc0;
    float mu1  = g_stats2[f1] * (1.f / NN);
    float var1 = g_stats2[64 + f1] * (1.f / NN) - mu1 * mu1;
    float sc1  = gamma[f1] * rsqrtf(var1 + EPS);
    float sh1  = beta[f1] - mu1 * sc1;
    float2 h = ((const float2*)g_h2)[(size_t)v * 32 + lane];
    float p = (h.x * sc0 + sh0) * awW[f0] + (h.y * sc1 + sh1) * awW[f1];
    #pragma unroll
    for (int o = 16; o; o >>= 1) p += __shfl_down_sync(0xffffffffu, p, o);
    if (lane == 0) g_w[v] = 1.f / (1.f + __expf(-(p + awb[0])));
}

// ---------------- pooling ----------------
__global__ __launch_bounds__(64) void k_pool(
    const int* __restrict__ ngr,
    const float* __restrict__ gamma, const float* __restrict__ beta)
{
    int g = blockIdx.x;
    int j = threadIdx.x;
    __shared__ int bnd[2];
    if (j < 2) {
        int key = g + j;
        int lo = 0, hi = NN;
        while (lo < hi) {
            int mid = (lo + hi) >> 1;
            if (ngr[mid] < key) lo = mid + 1; else hi = mid;
        }
        bnd[j] = lo;
    }
    float mu  = g_stats2[j] * (1.f / NN);
    float var = g_stats2[64 + j] * (1.f / NN) - mu * mu;
    float rs  = rsqrtf(var + EPS);
    float sc  = gamma[j] * rs;
    float sh  = beta[j] - mu * sc;
    __syncthreads();

    int s = bnd[0], e = bnd[1];
    float sum = 0.f, mx = -FLT_MAX;
    int n = s;
    for (; n + 4 <= e; n += 4) {
        float h0 = g_h2[(size_t)(n + 0) * 64 + j];
        float h1 = g_h2[(size_t)(n + 1) * 64 + j];
        float h2 = g_h2[(size_t)(n + 2) * 64 + j];
        float h3 = g_h2[(size_t)(n + 3) * 64 + j];
        float w0 = __ldg(&g_w[n + 0]);
        float w1 = __ldg(&g_w[n + 1]);
        float w2 = __ldg(&g_w[n + 2]);
        float w3 = __ldg(&g_w[n + 3]);
        h0 = h0 * sc + sh; h1 = h1 * sc + sh; h2 = h2 * sc + sh; h3 = h3 * sc + sh;
        sum += h0 * w0 + h1 * w1 + h2 * w2 + h3 * w3;
        mx = fmaxf(fmaxf(fmaxf(mx, h0), fmaxf(h1, h2)), h3);
    }
    for (; n < e; n++) {
        float h = g_h2[(size_t)n * 64 + j] * sc + sh;
        sum += h * __ldg(&g_w[n]);
        mx = fmaxf(mx, h);
    }
    g_hg[(size_t)g * 128 + j]      = sum;
    g_hg[(size_t)g * 128 + 64 + j] = mx;
}

// ---------------- classifier layer 1 ----------------
__global__ __launch_bounds__(128) void k_cls1(const float* __restrict__ W, const float* __restrict__ b) {
    __shared__ float xs[8][128];
    int tid = threadIdx.x;
    int row0 = blockIdx.x * 8;
    #pragma unroll
    for (int q = 0; q < 8; q++) {
        int lin = tid + q * 128;
        xs[lin >> 7][lin & 127] = g_hg[(size_t)row0 * 128 + lin];
    }
    __syncthreads();
    int j = tid;
    float acc[8] = {};
    for (int k = 0; k < 128; k++) {
        float w = __ldg(&W[k * 128 + j]);
        #pragma unroll
        for (int r = 0; r < 8; r++) acc[r] += xs[r][k] * w;
    }
    float bj = b[j];
    float lsum = 0.f, lsq = 0.f;
    #pragma unroll
    for (int r = 0; r < 8; r++) {
        float z = fmaxf(acc[r] + bj, 0.f);
        g_z[(size_t)(row0 + r) * 128 + j] = z;
        lsum += z; lsq += z * z;
    }
    atomicAdd(&g_statsC[j], lsum);
    atomicAdd(&g_statsC[128 + j], lsq);
}

// ---------------- classifier layer 2 ----------------
__global__ __launch_bounds__(256) void k_cls2(
    const float* __restrict__ cg, const float* __restrict__ cb,
    const float* __restrict__ W2, const float* __restrict__ b2, float* __restrict__ out)
{
    __shared__ float sc[128], sh[128];
    int tid = threadIdx.x;
    if (tid < 128) {
        float mu  = g_statsC[tid] * (1.f / NG);
        float var = g_statsC[128 + tid] * (1.f / NG) - mu * mu;
        float rs  = rsqrtf(var + EPS);
        float s = cg[tid] * rs;
        sc[tid] = s;
        sh[tid] = cb[tid] - mu * s;
    }
    __syncthreads();
    int idx = blockIdx.x * 256 + tid;
    if (idx >= NG * NT) return;
    int r = idx / NT, t = idx - r * NT;
    float acc = b2[t];
    for (int k = 0; k < 128; k++)
        acc += (g_z[(size_t)r * 128 + k] * sc[k] + sh[k]) * __ldg(&W2[k * NT + t]);
    out[idx] = acc;
}

// ---------------- launch (single stream, graph-capture safe) ----------------
extern "C" void kernel_launch(void* const* d_in, const int* in_sizes, int n_in,
                              void* d_out, int out_size) {
    const float* feats = (const float*)d_in[0];
    const int*   src   = (const int*)d_in[1];
    const int*   dst   = (const int*)d_in[2];
    const int*   ngr   = (const int*)d_in[3];
    const float* W0  = (const float*)d_in[4];
    const float* b0  = (const float*)d_in[5];
    const float* rW0 = (const float*)d_in[6];
    const float* rb0 = (const float*)d_in[7];
    const float* g0  = (const float*)d_in[8];
    const float* be0 = (const float*)d_in[9];
    const float* W1  = (const float*)d_in[10];
    const float* b1  = (const float*)d_in[11];
    const float* rW1 = (const float*)d_in[12];
    const float* rb1 = (const float*)d_in[13];
    const float* g1  = (const float*)d_in[14];
    const float* be1 = (const float*)d_in[15];
    const float* awW = (const float*)d_in[16];
    const float* awb = (const float*)d_in[17];
    const float* c1W = (const float*)d_in[18];
    const float* c1b = (const float*)d_in[19];
    const float* cg  = (const float*)d_in[20];
    const float* cb  = (const float*)d_in[21];
    const float* c2W = (const float*)d_in[22];
    const float* c2b = (const float*)d_in[23];
    float* out = (float*)d_out;

    float *p_h1, *p_h2, *p_s1, *p_s2;
    __half *p_xh, *p_h1h;
    cudaGetSymbolAddress((void**)&p_h1, g_h1);
    cudaGetSymbolAddress((void**)&p_h2, g_h2);
    cudaGetSymbolAddress((void**)&p_s1, g_stats1);
    cudaGetSymbolAddress((void**)&p_s2, g_stats2);
    cudaGetSymbolAddress((void**)&p_xh, g_xh);
    cudaGetSymbolAddress((void**)&p_h1h, g_h1h);

    const int GEMM_BLKS = (NN + 63) / 64;
    const int E4_BLKS   = (EE / 4 + 255) / 256;
    const int WTS_BLKS  = (NN * 32 + 255) / 256;
    const int CVT_BLKS  = (NN * FD / 4 + 255) / 256;

    // CSR build + feats fp16 conversion
    k_zero<<<(NN + 256) / 256, 256>>>();
    k_cvt<<<CVT_BLKS, 256>>>(feats, p_xh);
    k_deg<<<E4_BLKS, 256>>>(dst);
    k_scan1<<<NB1, 1024>>>();
    k_scan2<<<1, 128>>>();
    k_scatter<<<E4_BLKS, 256>>>(src, dst);

    // layer 1: gather raw feats (no BN), project, residual
    k_layer<<<GEMM_BLKS, 256>>>(feats, p_xh, nullptr, nullptr, nullptr,
                                W0, b0, rW0, rb0, p_h1, p_h1h, p_s1);

    // layer 2: gather raw h1, BN1 affine correction, project, residual
    k_layer<<<GEMM_BLKS, 256>>>(p_h1, p_h1h, p_s1, g0, be0,
                                W1, b1, rW1, rb1, p_h2, nullptr, p_s2);

    // pooling
    k_wts<<<WTS_BLKS, 256>>>(g1, be1, awW, awb);
    k_pool<<<NG, 64>>>(ngr, g1, be1);

    // classifier head
    k_cls1<<<NG / 8, 128>>>(c1W, c1b);
    k_cls2<<<(NG * NT + 255) / 256, 256>>>(cg, cb, c2W, c2b, out);
}

// round 10
// speedup vs baseline: 1.2385x; 1.2385x over previous
// R10: revert to R8 structure; quarter-warp (4 nodes/warp, uint4-lane) gather in k_post.
#include <cuda_runtime.h>
#include <cuda_fp16.h>
#include <math.h>
#include <float.h>

#define NN 100000
#define EE 1200000
#define FD 64
#define NG 1024
#define NT 12
#define CHID 128
#define EPS 1e-5f
#define NB1 98   // (NN+1023)/1024

// ---------------- scratch ----------------
__device__ __half g_mh[(size_t)NN * FD];  // projected messages (fp16)
__device__ float g_h1[(size_t)NN * FD];
__device__ float g_h2[(size_t)NN * FD];
__device__ float g_w[NN];
__device__ int   g_deg[NN + 1];
__device__ int   g_off[NN + 1];   // block-local exclusive prefix
__device__ int   g_cur[NN];       // scatter cursors (zeroed)
__device__ int   g_esrc[EE];
__device__ int   g_bsum[128];
__device__ int   g_bpre[128];
__device__ float g_stats1[2 * FD];
__device__ float g_stats2[2 * FD];
__device__ float g_statsC[2 * CHID];
__device__ float g_hg[(size_t)NG * 2 * FD];
__device__ float g_z[(size_t)NG * CHID];

// ---------------- zero ----------------
__global__ void k_zero() {
    int i = blockIdx.x * blockDim.x + threadIdx.x;
    if (i < NN + 1) g_deg[i] = 0;
    if (i < NN) g_cur[i] = 0;
    if (i < 2 * FD) { g_stats1[i] = 0.f; g_stats2[i] = 0.f; }
    if (i < 2 * CHID) g_statsC[i] = 0.f;
}

// ---------------- CSR build ----------------
__global__ void k_deg(const int* __restrict__ dst) {
    int i = blockIdx.x * blockDim.x + threadIdx.x;
    if (i < EE / 4) {
        int4 d = ((const int4*)dst)[i];
        atomicAdd(&g_deg[d.x], 1);
        atomicAdd(&g_deg[d.y], 1);
        atomicAdd(&g_deg[d.z], 1);
        atomicAdd(&g_deg[d.w], 1);
    }
}

__global__ __launch_bounds__(1024) void k_scan1() {
    int tid = threadIdx.x;
    int i = blockIdx.x * 1024 + tid;
    int d = (i < NN) ? g_deg[i] : 0;
    int lane = tid & 31, wid = tid >> 5;
    int v = d;
    #pragma unroll
    for (int o = 1; o < 32; o <<= 1) {
        int t = __shfl_up_sync(0xffffffffu, v, o);
        if (lane >= o) v += t;
    }
    __shared__ int ws[32];
    if (lane == 31) ws[wid] = v;
    __syncthreads();
    if (wid == 0) {
        int u = ws[lane];
        #pragma unroll
        for (int o = 1; o < 32; o <<= 1) {
            int t = __shfl_up_sync(0xffffffffu, u, o);
            if (lane >= o) u += t;
        }
        ws[lane] = u;
    }
    __syncthreads();
    int base = wid ? ws[wid - 1] : 0;
    if (i < NN) g_off[i] = base + v - d;
    if (tid == 0) g_bsum[blockIdx.x] = ws[31];
}

__global__ void k_scan2() {
    __shared__ int sh[128];
    int tid = threadIdx.x;
    int v = (tid < NB1) ? g_bsum[tid] : 0;
    sh[tid] = v;
    __syncthreads();
    for (int o = 1; o < 128; o <<= 1) {
        int t = (tid >= o) ? sh[tid - o] : 0;
        __syncthreads();
        sh[tid] += t;
        __syncthreads();
    }
    if (tid < NB1) g_bpre[tid] = sh[tid] - v;
}

__global__ void k_scatter(const int* __restrict__ src, const int* __restrict__ dst) {
    int i = blockIdx.x * blockDim.x + threadIdx.x;
    if (i < EE / 4) {
        int4 s = ((const int4*)src)[i];
        int4 d = ((const int4*)dst)[i];
        int o0 = __ldg(&g_off[d.x]) + __ldg(&g_bpre[d.x >> 10]);
        int o1 = __ldg(&g_off[d.y]) + __ldg(&g_bpre[d.y >> 10]);
        int o2 = __ldg(&g_off[d.z]) + __ldg(&g_bpre[d.z >> 10]);
        int o3 = __ldg(&g_off[d.w]) + __ldg(&g_bpre[d.w >> 10]);
        g_esrc[o0 + atomicAdd(&g_cur[d.x], 1)] = s.x;
        g_esrc[o1 + atomicAdd(&g_cur[d.y], 1)] = s.y;
        g_esrc[o2 + atomicAdd(&g_cur[d.z], 1)] = s.z;
        g_esrc[o3 + atomicAdd(&g_cur[d.w], 1)] = s.w;
    }
}

__device__ __forceinline__ int node_off(int v) {
    return g_off[v] + g_bpre[v >> 10];
}

// ---------------- GEMM: m = BN(x) @ W  -> fp16 ----------------
__global__ __launch_bounds__(256) void k_gemm(
    const float* __restrict__ x,
    const float* __restrict__ stats, const float* __restrict__ gamma, const float* __restrict__ beta,
    const float* __restrict__ W, __half* __restrict__ out)
{
    __shared__ float xs[64][68];
    __shared__ float Ws[64][64];
    __shared__ float scb[64], shb[64];
    int tid = threadIdx.x;

    if (tid < 64) {
        float sc = 1.f, sh = 0.f;
        if (stats) {
            float mu  = stats[tid] * (1.f / NN);
            float var = stats[64 + tid] * (1.f / NN) - mu * mu;
            float rs  = rsqrtf(var + EPS);
            sc = gamma[tid] * rs;
            sh = beta[tid] - mu * sc;
        }
        scb[tid] = sc; shb[tid] = sh;
    }
    #pragma unroll
    for (int q = 0; q < 16; q++) {
        int lin = tid + q * 256;
        ((float*)Ws)[lin] = W[lin];
    }
    __syncthreads();

    int row0 = blockIdx.x * 64;
    #pragma unroll
    for (int q = 0; q < 4; q++) {
        int lin = tid + q * 256;
        int r = lin >> 4;
        int c4 = (lin & 15) * 4;
        float4 v = make_float4(0.f, 0.f, 0.f, 0.f);
        if (row0 + r < NN) v = *(const float4*)(x + (size_t)(row0 + r) * 64 + c4);
        float4 o;
        o.x = v.x * scb[c4 + 0] + shb[c4 + 0];
        o.y = v.y * scb[c4 + 1] + shb[c4 + 1];
        o.z = v.z * scb[c4 + 2] + shb[c4 + 2];
        o.w = v.w * scb[c4 + 3] + shb[c4 + 3];
        *(float4*)&xs[r][c4] = o;
    }
    __syncthreads();

    int tx = tid & 15, ty = tid >> 4;
    int r0 = ty * 4, c0 = tx * 4;
    float acc[4][4] = {};
    #pragma unroll 4
    for (int k4 = 0; k4 < 64; k4 += 4) {
        float4 av[4];
        av[0] = *(const float4*)&xs[r0 + 0][k4];
        av[1] = *(const float4*)&xs[r0 + 1][k4];
        av[2] = *(const float4*)&xs[r0 + 2][k4];
        av[3] = *(const float4*)&xs[r0 + 3][k4];
        #pragma unroll
        for (int kk = 0; kk < 4; kk++) {
            float4 b = *(const float4*)&Ws[k4 + kk][c0];
            #pragma unroll
            for (int i = 0; i < 4; i++) {
                float a = (&av[i].x)[kk];
                acc[i][0] += a * b.x; acc[i][1] += a * b.y;
                acc[i][2] += a * b.z; acc[i][3] += a * b.w;
            }
        }
    }
    #pragma unroll
    for (int i = 0; i < 4; i++) {
        int r = row0 + r0 + i;
        if (r < NN) {
            __half2 p0 = __floats2half2_rn(acc[i][0], acc[i][1]);
            __half2 p1 = __floats2half2_rn(acc[i][2], acc[i][3]);
            uint2 pk = make_uint2(*(unsigned*)&p0, *(unsigned*)&p1);
            *(uint2*)(out + (size_t)r * 64 + c0) = pk;
        }
    }
}

// ---- post (fused): residual GEMM + quarter-warp fp16 gather + bias/relu + BN stats ----
__global__ __launch_bounds__(256) void k_post(
    const float* __restrict__ x,
    const float* __restrict__ stats, const float* __restrict__ gamma, const float* __restrict__ beta,
    const float* __restrict__ rW, const float* __restrict__ rb, const float* __restrict__ bias,
    float* __restrict__ outh, float* __restrict__ stats_out)
{
    __shared__ float xs[64][68];
    __shared__ float Ws[64][64];           // rW during k-loop, then agg tile
    __shared__ float scb[64], shb[64];
    __shared__ float s_sum[64], s_sq[64];
    int tid = threadIdx.x;
    int lane = tid & 31, wi = tid >> 5;

    if (tid < 64) {
        float sc = 1.f, sh = 0.f;
        if (stats) {
            float mu  = stats[tid] * (1.f / NN);
            float var = stats[64 + tid] * (1.f / NN) - mu * mu;
            float rs  = rsqrtf(var + EPS);
            sc = gamma[tid] * rs;
            sh = beta[tid] - mu * sc;
        }
        scb[tid] = sc; shb[tid] = sh;
        s_sum[tid] = 0.f; s_sq[tid] = 0.f;
    }
    #pragma unroll
    for (int q = 0; q < 16; q++) {
        int lin = tid + q * 256;
        ((float*)Ws)[lin] = rW[lin];
    }
    __syncthreads();

    int row0 = blockIdx.x * 64;
    #pragma unroll
    for (int q = 0; q < 4; q++) {
        int lin = tid + q * 256;
        int r = lin >> 4;
        int c4 = (lin & 15) * 4;
        float4 v = make_float4(0.f, 0.f, 0.f, 0.f);
        if (row0 + r < NN) v = *(const float4*)(x + (size_t)(row0 + r) * 64 + c4);
        float4 o;
        o.x = v.x * scb[c4 + 0] + shb[c4 + 0];
        o.y = v.y * scb[c4 + 1] + shb[c4 + 1];
        o.z = v.z * scb[c4 + 2] + shb[c4 + 2];
        o.w = v.w * scb[c4 + 3] + shb[c4 + 3];
        *(float4*)&xs[r][c4] = o;
    }
    __syncthreads();

    int tx = tid & 15, ty = tid >> 4;
    int r0 = ty * 4, c0 = tx * 4;
    float acc[4][4] = {};
    #pragma unroll 4
    for (int k4 = 0; k4 < 64; k4 += 4) {
        float4 av[4];
        av[0] = *(const float4*)&xs[r0 + 0][k4];
        av[1] = *(const float4*)&xs[r0 + 1][k4];
        av[2] = *(const float4*)&xs[r0 + 2][k4];
        av[3] = *(const float4*)&xs[r0 + 3][k4];
        #pragma unroll
        for (int kk = 0; kk < 4; kk++) {
            float4 b = *(const float4*)&Ws[k4 + kk][c0];
            #pragma unroll
            for (int i = 0; i < 4; i++) {
                float a = (&av[i].x)[kk];
                acc[i][0] += a * b.x; acc[i][1] += a * b.y;
                acc[i][2] += a * b.z; acc[i][3] += a * b.w;
            }
        }
    }
    __syncthreads();   // done with rW in Ws

    // ---- gather: warp split into four 8-lane quarters, one node each; uint4/lane = full row ----
    float* aggs = &Ws[0][0];
    const uint4* m8 = (const uint4*)g_mh;           // 8 uint4 per node row (128 B)
    int lane8 = lane & 7;
    int qb    = lane & 24;                           // quarter base lane: 0,8,16,24
    for (int t = 0; t < 2; t++) {
        int r = wi * 8 + t * 4 + (qb >> 3);
        int v = row0 + r;
        float a0 = 0.f, a1 = 0.f, a2 = 0.f, a3 = 0.f;
        float a4 = 0.f, a5 = 0.f, a6 = 0.f, a7 = 0.f;
        int s = 0, cnt = 0;
        if (v < NN) {
            s = node_off(v);
            int e = (v + 1 < NN) ? node_off(v + 1) : EE;
            cnt = e - s;
        }
        int m = max(cnt, __shfl_xor_sync(0xffffffffu, cnt, 8));
        int iters = max(m, __shfl_xor_sync(0xffffffffu, m, 16));
        for (int base = 0; base < iters; base += 8) {
            int my = base + lane8;
            int idx = (my < cnt) ? __ldg(&g_esrc[s + my]) : -1;
            #pragma unroll
            for (int g = 0; g < 8; g += 4) {
                int s0 = __shfl_sync(0xffffffffu, idx, qb + g + 0);
                int s1 = __shfl_sync(0xffffffffu, idx, qb + g + 1);
                int s2 = __shfl_sync(0xffffffffu, idx, qb + g + 2);
                int s3 = __shfl_sync(0xffffffffu, idx, qb + g + 3);
                uint4 z = make_uint4(0u, 0u, 0u, 0u);
                uint4 q0 = (s0 >= 0) ? __ldg(&m8[(size_t)s0 * 8 + lane8]) : z;
                uint4 q1 = (s1 >= 0) ? __ldg(&m8[(size_t)s1 * 8 + lane8]) : z;
                uint4 q2 = (s2 >= 0) ? __ldg(&m8[(size_t)s2 * 8 + lane8]) : z;
                uint4 q3 = (s3 >= 0) ? __ldg(&m8[(size_t)s3 * 8 + lane8]) : z;
                float2 f0, f1, f2, f3;
                f0 = __half22float2(*(__half2*)&q0.x); f1 = __half22float2(*(__half2*)&q1.x);
                f2 = __half22float2(*(__half2*)&q2.x); f3 = __half22float2(*(__half2*)&q3.x);
                a0 += (f0.x + f1.x) + (f2.x + f3.x);
                a1 += (f0.y + f1.y) + (f2.y + f3.y);
                f0 = __half22float2(*(__half2*)&q0.y); f1 = __half22float2(*(__half2*)&q1.y);
                f2 = __half22float2(*(__half2*)&q2.y); f3 = __half22float2(*(__half2*)&q3.y);
                a2 += (f0.x + f1.x) + (f2.x + f3.x);
                a3 += (f0.y + f1.y) + (f2.y + f3.y);
                f0 = __half22float2(*(__half2*)&q0.z); f1 = __half22float2(*(__half2*)&q1.z);
                f2 = __half22float2(*(__half2*)&q2.z); f3 = __half22float2(*(__half2*)&q3.z);
                a4 += (f0.x + f1.x) + (f2.x + f3.x);
                a5 += (f0.y + f1.y) + (f2.y + f3.y);
                f0 = __half22float2(*(__half2*)&q0.w); f1 = __half22float2(*(__half2*)&q1.w);
                f2 = __half22float2(*(__half2*)&q2.w); f3 = __half22float2(*(__half2*)&q3.w);
                a6 += (f0.x + f1.x) + (f2.x + f3.x);
                a7 += (f0.y + f1.y) + (f2.y + f3.y);
            }
        }
        if (v < NN) {
            float* dst = aggs + r * 64 + lane8 * 8;
            *(float4*)(dst + 0) = make_float4(a0, a1, a2, a3);
            *(float4*)(dst + 4) = make_float4(a4, a5, a6, a7);
        }
    }
    __syncthreads();

    // ---- epilogue ----
    float4 b4  = *(const float4*)(bias + c0);
    float4 rb4 = *(const float4*)(rb + c0);
    float lsum[4] = {0.f, 0.f, 0.f, 0.f};
    float lsq[4]  = {0.f, 0.f, 0.f, 0.f};
    #pragma unroll
    for (int i = 0; i < 4; i++) {
        int r = row0 + r0 + i;
        if (r < NN) {
            float4 av = *(const float4*)(aggs + (r0 + i) * 64 + c0);
            float h0 = fmaxf(av.x + b4.x, 0.f) + fmaxf(acc[i][0] + rb4.x, 0.f);
            float h1 = fmaxf(av.y + b4.y, 0.f) + fmaxf(acc[i][1] + rb4.y, 0.f);
            float h2 = fmaxf(av.z + b4.z, 0.f) + fmaxf(acc[i][2] + rb4.z, 0.f);
            float h3 = fmaxf(av.w + b4.w, 0.f) + fmaxf(acc[i][3] + rb4.w, 0.f);
            *(float4*)(outh + (size_t)r * 64 + c0) = make_float4(h0, h1, h2, h3);
            lsum[0] += h0; lsq[0] += h0 * h0;
            lsum[1] += h1; lsq[1] += h1 * h1;
            lsum[2] += h2; lsq[2] += h2 * h2;
            lsum[3] += h3; lsq[3] += h3 * h3;
        }
    }
    #pragma unroll
    for (int j = 0; j < 4; j++) {
        atomicAdd(&s_sum[c0 + j], lsum[j]);
        atomicAdd(&s_sq[c0 + j], lsq[j]);
    }
    __syncthreads();
    if (tid < 64) {
        atomicAdd(&stats_out[tid], s_sum[tid]);
        atomicAdd(&stats_out[64 + tid], s_sq[tid]);
    }
}

// ---------------- atom weights ----------------
__global__ __launch_bounds__(256) void k_wts(
    const float* __restrict__ gamma, const float* __restrict__ beta,
    const float* __restrict__ awW, const float* __restrict__ awb)
{
    int gt = blockIdx.x * blockDim.x + threadIdx.x;
    int v = gt >> 5;
    int lane = gt & 31;
    if (v >= NN) return;
    int f0 = 2 * lane, f1 = f0 + 1;
    float mu0  = g_stats2[f0] * (1.f / NN);
    float var0 = g_stats2[64 + f0] * (1.f / NN) - mu0 * mu0;
    float sc0  = gamma[f0] * rsqrtf(var0 + EPS);
    float sh0  = beta[f0] - mu0 * sc0;
    float mu1  = g_stats2[f1] * (1.f / NN);
    float var1 = g_stats2[64 + f1] * (1.f / NN) - mu1 * mu1;
    float sc1  = gamma[f1] * rsqrtf(var1 + EPS);
    float sh1  = beta[f1] - mu1 * sc1;
    float2 h = ((const float2*)g_h2)[(size_t)v * 32 + lane];
    float p = (h.x * sc0 + sh0) * awW[f0] + (h.y * sc1 + sh1) * awW[f1];
    #pragma unroll
    for (int o = 16; o; o >>= 1) p += __shfl_down_sync(0xffffffffu, p, o);
    if (lane == 0) g_w[v] = 1.f / (1.f + __expf(-(p + awb[0])));
}

// ---------------- pooling ----------------
__global__ __launch_bounds__(64) void k_pool(
    const int* __restrict__ ngr,
    const float* __restrict__ gamma, const float* __restrict__ beta)
{
    int g = blockIdx.x;
    int j = threadIdx.x;
    __shared__ int bnd[2];
    if (j < 2) {
        int key = g + j;
        int lo = 0, hi = NN;
        while (lo < hi) {
            int mid = (lo + hi) >> 1;
            if (ngr[mid] < key) lo = mid + 1; else hi = mid;
        }
        bnd[j] = lo;
    }
    float mu  = g_stats2[j] * (1.f / NN);
    float var = g_stats2[64 + j] * (1.f / NN) - mu * mu;
    float rs  = rsqrtf(var + EPS);
    float sc  = gamma[j] * rs;
    float sh  = beta[j] - mu * sc;
    __syncthreads();

    int s = bnd[0], e = bnd[1];
    float sum = 0.f, mx = -FLT_MAX;
    int n = s;
    for (; n + 4 <= e; n += 4) {
        float h0 = g_h2[(size_t)(n + 0) * 64 + j];
        float h1 = g_h2[(size_t)(n + 1) * 64 + j];
        float h2 = g_h2[(size_t)(n + 2) * 64 + j];
        float h3 = g_h2[(size_t)(n + 3) * 64 + j];
        float w0 = __ldg(&g_w[n + 0]);
        float w1 = __ldg(&g_w[n + 1]);
        float w2 = __ldg(&g_w[n + 2]);
        float w3 = __ldg(&g_w[n + 3]);
        h0 = h0 * sc + sh; h1 = h1 * sc + sh; h2 = h2 * sc + sh; h3 = h3 * sc + sh;
        sum += h0 * w0 + h1 * w1 + h2 * w2 + h3 * w3;
        mx = fmaxf(fmaxf(fmaxf(mx, h0), fmaxf(h1, h2)), h3);
    }
    for (; n < e; n++) {
        float h = g_h2[(size_t)n * 64 + j] * sc + sh;
        sum += h * __ldg(&g_w[n]);
        mx = fmaxf(mx, h);
    }
    g_hg[(size_t)g * 128 + j]      = sum;
    g_hg[(size_t)g * 128 + 64 + j] = mx;
}

// ---------------- classifier layer 1 ----------------
__global__ __launch_bounds__(128) void k_cls1(const float* __restrict__ W, const float* __restrict__ b) {
    __shared__ float xs[8][128];
    int tid = threadIdx.x;
    int row0 = blockIdx.x * 8;
    #pragma unroll
    for (int q = 0; q < 8; q++) {
        int lin = tid + q * 128;
        xs[lin >> 7][lin & 127] = g_hg[(size_t)row0 * 128 + lin];
    }
    __syncthreads();
    int j = tid;
    float acc[8] = {};
    for (int k = 0; k < 128; k++) {
        float w = __ldg(&W[k * 128 + j]);
        #pragma unroll
        for (int r = 0; r < 8; r++) acc[r] += xs[r][k] * w;
    }
    float bj = b[j];
    float lsum = 0.f, lsq = 0.f;
    #pragma unroll
    for (int r = 0; r < 8; r++) {
        float z = fmaxf(acc[r] + bj, 0.f);
        g_z[(size_t)(row0 + r) * 128 + j] = z;
        lsum += z; lsq += z * z;
    }
    atomicAdd(&g_statsC[j], lsum);
    atomicAdd(&g_statsC[128 + j], lsq);
}

// ---------------- classifier layer 2 ----------------
__global__ __launch_bounds__(256) void k_cls2(
    const float* __restrict__ cg, const float* __restrict__ cb,
    const float* __restrict__ W2, const float* __restrict__ b2, float* __restrict__ out)
{
    __shared__ float sc[128], sh[128];
    int tid = threadIdx.x;
    if (tid < 128) {
        float mu  = g_statsC[tid] * (1.f / NG);
        float var = g_statsC[128 + tid] * (1.f / NG) - mu * mu;
        float rs  = rsqrtf(var + EPS);
        float s = cg[tid] * rs;
        sc[tid] = s;
        sh[tid] = cb[tid] - mu * s;
    }
    __syncthreads();
    int idx = blockIdx.x * 256 + tid;
    if (idx >= NG * NT) return;
    int r = idx / NT, t = idx - r * NT;
    float acc = b2[t];
    for (int k = 0; k < 128; k++)
        acc += (g_z[(size_t)r * 128 + k] * sc[k] + sh[k]) * __ldg(&W2[k * NT + t]);
    out[idx] = acc;
}

// ---------------- launch (single stream, graph-capture safe) ----------------
extern "C" void kernel_launch(void* const* d_in, const int* in_sizes, int n_in,
                              void* d_out, int out_size) {
    const float* feats = (const float*)d_in[0];
    const int*   src   = (const int*)d_in[1];
    const int*   dst   = (const int*)d_in[2];
    const int*   ngr   = (const int*)d_in[3];
    const float* W0  = (const float*)d_in[4];
    const float* b0  = (const float*)d_in[5];
    const float* rW0 = (const float*)d_in[6];
    const float* rb0 = (const float*)d_in[7];
    const float* g0  = (const float*)d_in[8];
    const float* be0 = (const float*)d_in[9];
    const float* W1  = (const float*)d_in[10];
    const float* b1  = (const float*)d_in[11];
    const float* rW1 = (const float*)d_in[12];
    const float* rb1 = (const float*)d_in[13];
    const float* g1  = (const float*)d_in[14];
    const float* be1 = (const float*)d_in[15];
    const float* awW = (const float*)d_in[16];
    const float* awb = (const float*)d_in[17];
    const float* c1W = (const float*)d_in[18];
    const float* c1b = (const float*)d_in[19];
    const float* cg  = (const float*)d_in[20];
    const float* cb  = (const float*)d_in[21];
    const float* c2W = (const float*)d_in[22];
    const float* c2b = (const float*)d_in[23];
    float* out = (float*)d_out;

    float *p_h1, *p_h2, *p_s1, *p_s2;
    __half* p_m;
    cudaGetSymbolAddress((void**)&p_h1, g_h1);
    cudaGetSymbolAddress((void**)&p_h2, g_h2);
    cudaGetSymbolAddress((void**)&p_s1, g_stats1);
    cudaGetSymbolAddress((void**)&p_s2, g_stats2);
    cudaGetSymbolAddress((void**)&p_m, g_mh);

    const int GEMM_BLKS = (NN + 63) / 64;
    const int E4_BLKS   = (EE / 4 + 255) / 256;
    const int WTS_BLKS  = (NN * 32 + 255) / 256;

    // CSR build with layer-1 GEMM interleaved (independent work fills scan gaps)
    k_zero<<<(NN + 256) / 256, 256>>>();
    k_deg<<<E4_BLKS, 256>>>(dst);
    k_scan1<<<NB1, 1024>>>();
    k_gemm<<<GEMM_BLKS, 256>>>(feats, nullptr, nullptr, nullptr, W0, p_m);
    k_scan2<<<1, 128>>>();
    k_scatter<<<E4_BLKS, 256>>>(src, dst);

    // layer 1 (rest)
    k_post<<<GEMM_BLKS, 256>>>(feats, nullptr, nullptr, nullptr, rW0, rb0, b0, p_h1, p_s1);

    // layer 2
    k_gemm<<<GEMM_BLKS, 256>>>(p_h1, p_s1, g0, be0, W1, p_m);
    k_post<<<GEMM_BLKS, 256>>>(p_h1, p_s1, g0, be0, rW1, rb1, b1, p_h2, p_s2);

    // pooling
    k_wts<<<WTS_BLKS, 256>>>(g1, be1, awW, awb);
    k_pool<<<NG, 64>>>(ngr, g1, be1);

    // classifier head
    k_cls1<<<NG / 8, 128>>>(c1W, c1b);
    k_cls2<<<(NG * NT + 255) / 256, 256>>>(cg, cb, c2W, c2b, out);
}